// round 8
// baseline (speedup 1.0000x reference)
#include <cuda_runtime.h>
#include <cuda_fp16.h>

#define N_NODES 50000
#define N_EDGES 600000
#define HID 128
#define NG 512
#define EPS 1e-5f
#define NBLK ((N_NODES + 1023) / 1024)   // 49
#define PITCH 136                         // smem half pitch (272B, ldmatrix conflict-free)

// ---------------- device scratch ----------------
__device__ float  g_anchor[N_NODES * HID]; // fp32 APPNP anchor h0
__device__ float  g_buf2[N_NODES * HID];   // gemm output (pre-BN)
__device__ uint2  g_ha[N_NODES * 32];      // half feature buffer A
__device__ uint2  g_hb[N_NODES * 32];      // half feature buffer B
__device__ __half g_wh[3 * HID * HID];     // half conv weights
__device__ int    g_deg[N_NODES];
__device__ float  g_dinv[N_NODES];
__device__ int    g_rowptr[N_NODES + 1];
__device__ int    g_cursor[N_NODES];
__device__ int    g_bsum[NBLK];
__device__ int2   g_epack[N_EDGES];        // packed {src, weight bits}
__device__ int    g_gstart[NG + 1];        // graph segment starts (batch is sorted)
__device__ float  g_vn[NG * HID];
__device__ float  g_z[NG * 2 * HID];
__device__ float  g_t[NG * HID];
__device__ float  g_cs[8 * 512];           // per-BN-instance column sum/sumsq

// ---------------- half helpers ----------------
__device__ __forceinline__ float4 h2f4(uint2 u) {
    __half2 a = *(__half2*)&u.x, b = *(__half2*)&u.y;
    float2 fa = __half22float2(a), fb = __half22float2(b);
    return make_float4(fa.x, fa.y, fb.x, fb.y);
}
__device__ __forceinline__ uint2 f2h4(float4 v) {
    __half2 a = __floats2half2_rn(v.x, v.y), b = __floats2half2_rn(v.z, v.w);
    uint2 u;
    u.x = *(unsigned*)&a;
    u.y = *(unsigned*)&b;
    return u;
}

// ---------------- setup ----------------
__global__ void k_init(const float* __restrict__ vn_emb, const float* __restrict__ W) {
    int i = blockIdx.x * blockDim.x + threadIdx.x;
    if (i < N_NODES) g_deg[i] = 0;
    if (i < NG * HID) g_vn[i] = vn_emb[i & (HID - 1)];
    if (i < 3 * HID * HID) g_wh[i] = __float2half(W[i]);
    if (i < 8 * 512) g_cs[i] = 0.f;
}

// fused: graph segment starts + x -> half conversion
__global__ void k_pre(const int* __restrict__ batch, const float4* __restrict__ x,
                      uint2* __restrict__ out) {
    int i = blockIdx.x * blockDim.x + threadIdx.x;
    if (i < N_NODES * 32) out[i] = f2h4(x[i]);
    if (i < N_NODES) {
        int b = batch[i];
        int bp = (i == 0) ? -1 : batch[i - 1];
        for (int g = bp + 1; g <= b; ++g) g_gstart[g] = i;
        if (i == N_NODES - 1) {
            for (int g = b + 1; g <= NG; ++g) g_gstart[g] = N_NODES;
        }
    }
}

__global__ void k_hist(const int* __restrict__ dst) {
    int e = blockIdx.x * blockDim.x + threadIdx.x;
    if (e < N_EDGES) atomicAdd(&g_deg[dst[e]], 1);
}

__global__ void k_scan1() {
    __shared__ int ws[32];
    int tid = threadIdx.x;
    int i = blockIdx.x * 1024 + tid;
    int v = (i < N_NODES) ? g_deg[i] : 0;
    if (i < N_NODES) g_dinv[i] = rsqrtf((float)(v + 1));
    int r = v;
    #pragma unroll
    for (int o = 16; o; o >>= 1) r += __shfl_down_sync(0xffffffffu, r, o);
    if ((tid & 31) == 0) ws[tid >> 5] = r;
    __syncthreads();
    if (tid < 32) {
        int t = ws[tid];
        #pragma unroll
        for (int o = 16; o; o >>= 1) t += __shfl_down_sync(0xffffffffu, t, o);
        if (tid == 0) g_bsum[blockIdx.x] = t;
    }
}

// fused scan: each block computes its chunk offset from g_bsum, then intra-chunk scan
__global__ void k_scan3() {
    __shared__ int wsum[32];
    __shared__ int sb[64];
    int tid = threadIdx.x;
    if (tid < 64) {
        int v = (tid < NBLK) ? g_bsum[tid] : 0;
        sb[tid] = v;
    }
    __syncthreads();
    #pragma unroll
    for (int o = 1; o < 64; o <<= 1) {
        int u = 0;
        if (tid < 64 && tid >= o) u = sb[tid - o];
        __syncthreads();
        if (tid < 64) sb[tid] += u;
        __syncthreads();
    }
    if (blockIdx.x == 0 && tid == NBLK - 1) g_rowptr[N_NODES] = sb[tid];
    int boff = (blockIdx.x == 0) ? 0 : sb[blockIdx.x - 1];

    int i = blockIdx.x * 1024 + tid;
    int v = (i < N_NODES) ? g_deg[i] : 0;
    int x = v;
    #pragma unroll
    for (int o = 1; o < 32; o <<= 1) {
        int y = __shfl_up_sync(0xffffffffu, x, o);
        if ((tid & 31) >= o) x += y;
    }
    if ((tid & 31) == 31) wsum[tid >> 5] = x;
    __syncthreads();
    if (tid < 32) {
        int s = wsum[tid];
        int z = s;
        #pragma unroll
        for (int o = 1; o < 32; o <<= 1) {
            int y = __shfl_up_sync(0xffffffffu, z, o);
            if (tid >= o) z += y;
        }
        wsum[tid] = z - s;
    }
    __syncthreads();
    int excl = boff + (x - v) + wsum[tid >> 5];
    if (i < N_NODES) { g_rowptr[i] = excl; g_cursor[i] = excl; }
}

__global__ void k_fill(const int* __restrict__ src, const int* __restrict__ dst) {
    int e = blockIdx.x * blockDim.x + threadIdx.x;
    if (e >= N_EDGES) return;
    int d = dst[e], s = src[e];
    int pos = atomicAdd(&g_cursor[d], 1);
    g_epack[pos] = make_int2(s, __float_as_int(g_dinv[s] * g_dinv[d]));
}

// ---------------- propagation (half gather, 4-way unrolled for MLP) ----------------
__device__ __forceinline__ float4 gather(const uint2* __restrict__ in, int node, int lane) {
    float dv = g_dinv[node];
    float w0 = dv * dv;
    float4 p = h2f4(__ldg(&in[node * 32 + lane]));
    float4 acc = make_float4(w0 * p.x, w0 * p.y, w0 * p.z, w0 * p.w);
    int e = __ldg(&g_rowptr[node]), end = __ldg(&g_rowptr[node + 1]);
    // 4-way unrolled main loop: 4 independent epack loads, then 4 independent
    // feature-row loads in flight (MLP ~4 on the dominant chain)
    for (; e + 3 < end; e += 4) {
        int2 e0 = __ldg(&g_epack[e]);
        int2 e1 = __ldg(&g_epack[e + 1]);
        int2 e2 = __ldg(&g_epack[e + 2]);
        int2 e3 = __ldg(&g_epack[e + 3]);
        float4 q0 = h2f4(__ldg(&in[e0.x * 32 + lane]));
        float4 q1 = h2f4(__ldg(&in[e1.x * 32 + lane]));
        float4 q2 = h2f4(__ldg(&in[e2.x * 32 + lane]));
        float4 q3 = h2f4(__ldg(&in[e3.x * 32 + lane]));
        float w0e = __int_as_float(e0.y), w1e = __int_as_float(e1.y);
        float w2e = __int_as_float(e2.y), w3e = __int_as_float(e3.y);
        acc.x = fmaf(w0e, q0.x, acc.x); acc.y = fmaf(w0e, q0.y, acc.y);
        acc.z = fmaf(w0e, q0.z, acc.z); acc.w = fmaf(w0e, q0.w, acc.w);
        acc.x = fmaf(w1e, q1.x, acc.x); acc.y = fmaf(w1e, q1.y, acc.y);
        acc.z = fmaf(w1e, q1.z, acc.z); acc.w = fmaf(w1e, q1.w, acc.w);
        acc.x = fmaf(w2e, q2.x, acc.x); acc.y = fmaf(w2e, q2.y, acc.y);
        acc.z = fmaf(w2e, q2.z, acc.z); acc.w = fmaf(w2e, q2.w, acc.w);
        acc.x = fmaf(w3e, q3.x, acc.x); acc.y = fmaf(w3e, q3.y, acc.y);
        acc.z = fmaf(w3e, q3.z, acc.z); acc.w = fmaf(w3e, q3.w, acc.w);
    }
    if (e + 1 < end) {
        int2 e0 = __ldg(&g_epack[e]);
        int2 e1 = __ldg(&g_epack[e + 1]);
        float4 q0 = h2f4(__ldg(&in[e0.x * 32 + lane]));
        float4 q1 = h2f4(__ldg(&in[e1.x * 32 + lane]));
        float w0e = __int_as_float(e0.y), w1e = __int_as_float(e1.y);
        acc.x = fmaf(w0e, q0.x, acc.x); acc.y = fmaf(w0e, q0.y, acc.y);
        acc.z = fmaf(w0e, q0.z, acc.z); acc.w = fmaf(w0e, q0.w, acc.w);
        acc.x = fmaf(w1e, q1.x, acc.x); acc.y = fmaf(w1e, q1.y, acc.y);
        acc.z = fmaf(w1e, q1.z, acc.z); acc.w = fmaf(w1e, q1.w, acc.w);
        e += 2;
    }
    if (e < end) {
        int2 e0 = __ldg(&g_epack[e]);
        float w0e = __int_as_float(e0.y);
        float4 q0 = h2f4(__ldg(&in[e0.x * 32 + lane]));
        acc.x = fmaf(w0e, q0.x, acc.x); acc.y = fmaf(w0e, q0.y, acc.y);
        acc.z = fmaf(w0e, q0.z, acc.z); acc.w = fmaf(w0e, q0.w, acc.w);
    }
    return acc;
}

// layer prop: half output (GEMM A operand)
__global__ void k_prop_h(const uint2* __restrict__ in, uint2* __restrict__ out) {
    int node = (blockIdx.x * blockDim.x + threadIdx.x) >> 5;
    if (node >= N_NODES) return;
    int lane = threadIdx.x & 31;
    out[node * 32 + lane] = f2h4(gather(in, node, lane));
}

__global__ void k_prop_ap(const uint2* __restrict__ in, const float4* __restrict__ h0,
                          uint2* __restrict__ out) {
    int node = (blockIdx.x * blockDim.x + threadIdx.x) >> 5;
    if (node >= N_NODES) return;
    int lane = threadIdx.x & 31;
    float4 acc = gather(in, node, lane);
    float4 a0 = __ldg(&h0[node * 32 + lane]);
    float4 o = make_float4(fmaf(0.2f, acc.x, 0.8f * a0.x), fmaf(0.2f, acc.y, 0.8f * a0.y),
                           fmaf(0.2f, acc.z, 0.8f * a0.z), fmaf(0.2f, acc.w, 0.8f * a0.w));
    out[node * 32 + lane] = f2h4(o);
}

// ---------------- tensor-core GEMM (HMMA m16n8k16, fp32 acc, fused BN stats) ----------
__device__ __forceinline__ void ldsm_x4(unsigned addr, unsigned& r0, unsigned& r1,
                                        unsigned& r2, unsigned& r3) {
    asm volatile("ldmatrix.sync.aligned.m8n8.x4.shared.b16 {%0,%1,%2,%3}, [%4];"
                 : "=r"(r0), "=r"(r1), "=r"(r2), "=r"(r3) : "r"(addr));
}
__device__ __forceinline__ void ldsm_x4t(unsigned addr, unsigned& r0, unsigned& r1,
                                         unsigned& r2, unsigned& r3) {
    asm volatile("ldmatrix.sync.aligned.m8n8.x4.trans.shared.b16 {%0,%1,%2,%3}, [%4];"
                 : "=r"(r0), "=r"(r1), "=r"(r2), "=r"(r3) : "r"(addr));
}
__device__ __forceinline__ void mma16816(float* d, unsigned a0, unsigned a1, unsigned a2,
                                         unsigned a3, unsigned b0, unsigned b1) {
    asm volatile(
        "mma.sync.aligned.m16n8k16.row.col.f32.f16.f16.f32 "
        "{%0,%1,%2,%3},{%4,%5,%6,%7},{%8,%9},{%0,%1,%2,%3};"
        : "+f"(d[0]), "+f"(d[1]), "+f"(d[2]), "+f"(d[3])
        : "r"(a0), "r"(a1), "r"(a2), "r"(a3), "r"(b0), "r"(b1));
}

__global__ void __launch_bounds__(256) gemm_mma(
        const __half* __restrict__ A, const __half* __restrict__ Wh,
        const float* __restrict__ bias, float* __restrict__ C,
        float* __restrict__ cs) {
    extern __shared__ __half sh[];
    __half* As = sh;                       // 128 x PITCH
    __half* Ws = sh + 128 * PITCH;         // 128 x PITCH
    float* scs = (float*)(sh + 2 * 128 * PITCH);  // 256 floats
    int tid = threadIdx.x;
    scs[tid] = 0.f;
    int r0 = blockIdx.x * 128;
    #pragma unroll
    for (int it = 0; it < 8; ++it) {
        int i = tid + it * 256;
        int row = i >> 4, cu = i & 15;
        uint4 v = make_uint4(0u, 0u, 0u, 0u);
        if (r0 + row < N_NODES) v = *(const uint4*)(A + (size_t)(r0 + row) * 128 + cu * 8);
        *(uint4*)(As + row * PITCH + cu * 8) = v;
        *(uint4*)(Ws + row * PITCH + cu * 8) = *(const uint4*)(Wh + row * 128 + cu * 8);
    }
    __syncthreads();

    int wid = tid >> 5, lane = tid & 31;
    int wm = wid >> 1, wn = wid & 1;
    float acc[2][8][4];
    #pragma unroll
    for (int a = 0; a < 2; a++)
        #pragma unroll
        for (int b = 0; b < 8; b++)
            #pragma unroll
            for (int c = 0; c < 4; c++) acc[a][b][c] = 0.f;

    unsigned asBase = (unsigned)__cvta_generic_to_shared(As);
    unsigned wsBase = (unsigned)__cvta_generic_to_shared(Ws);
    unsigned aAddr = asBase + (unsigned)(((wm * 32 + (lane & 15)) * PITCH + (lane >> 4) * 8) * 2);
    unsigned bAddr = wsBase + (unsigned)(((lane & 15) * PITCH + wn * 64 + (lane >> 4) * 8) * 2);

    #pragma unroll
    for (int ks = 0; ks < 8; ++ks) {
        unsigned a0r[4], a1r[4];
        ldsm_x4(aAddr + ks * 32, a0r[0], a0r[1], a0r[2], a0r[3]);
        ldsm_x4(aAddr + ks * 32 + 16 * PITCH * 2, a1r[0], a1r[1], a1r[2], a1r[3]);
        unsigned br[4][4];
        #pragma unroll
        for (int nfp = 0; nfp < 4; nfp++)
            ldsm_x4t(bAddr + ks * 16 * PITCH * 2 + nfp * 32,
                     br[nfp][0], br[nfp][1], br[nfp][2], br[nfp][3]);
        #pragma unroll
        for (int nfp = 0; nfp < 4; nfp++) {
            mma16816(acc[0][2 * nfp],     a0r[0], a0r[1], a0r[2], a0r[3], br[nfp][0], br[nfp][1]);
            mma16816(acc[0][2 * nfp + 1], a0r[0], a0r[1], a0r[2], a0r[3], br[nfp][2], br[nfp][3]);
            mma16816(acc[1][2 * nfp],     a1r[0], a1r[1], a1r[2], a1r[3], br[nfp][0], br[nfp][1]);
            mma16816(acc[1][2 * nfp + 1], a1r[0], a1r[1], a1r[2], a1r[3], br[nfp][2], br[nfp][3]);
        }
    }

    int cb = wn * 64;
    #pragma unroll
    for (int nf = 0; nf < 8; ++nf) {
        int col = cb + nf * 8 + (lane & 3) * 2;
        float b0 = __ldg(&bias[col]), b1 = __ldg(&bias[col + 1]);
        float s0 = 0.f, s1 = 0.f, q0 = 0.f, q1 = 0.f;
        #pragma unroll
        for (int mf = 0; mf < 2; ++mf) {
            int r = r0 + wm * 32 + mf * 16 + (lane >> 2);
            float v0 = acc[mf][nf][0] + b0, v1 = acc[mf][nf][1] + b1;
            if (r < N_NODES) {
                *(float2*)&C[(size_t)r * 128 + col] = make_float2(v0, v1);
                s0 += v0; s1 += v1;
                q0 = fmaf(v0, v0, q0); q1 = fmaf(v1, v1, q1);
            }
            int r2 = r + 8;
            float v2 = acc[mf][nf][2] + b0, v3 = acc[mf][nf][3] + b1;
            if (r2 < N_NODES) {
                *(float2*)&C[(size_t)r2 * 128 + col] = make_float2(v2, v3);
                s0 += v2; s1 += v3;
                q0 = fmaf(v2, v2, q0); q1 = fmaf(v3, v3, q1);
            }
        }
        #pragma unroll
        for (int off = 16; off >= 4; off >>= 1) {
            s0 += __shfl_xor_sync(0xffffffffu, s0, off);
            s1 += __shfl_xor_sync(0xffffffffu, s1, off);
            q0 += __shfl_xor_sync(0xffffffffu, q0, off);
            q1 += __shfl_xor_sync(0xffffffffu, q1, off);
        }
        if (lane < 4) {
            atomicAdd(&scs[col], s0);
            atomicAdd(&scs[col + 1], s1);
            atomicAdd(&scs[128 + col], q0);
            atomicAdd(&scs[128 + col + 1], q1);
        }
    }
    __syncthreads();
    atomicAdd(&cs[tid], scs[tid]);
}

// ---------------- BN apply (16 rows/block, no atomics) ----------------
__global__ void bn_apply_layer(const float* __restrict__ x, const float* __restrict__ gamma,
                               const float* __restrict__ beta, const int* __restrict__ batch,
                               const float* __restrict__ cs, unsigned* __restrict__ out16) {
    int c = threadIdx.x;
    const float inv_n = 1.f / N_NODES;
    float m = cs[c] * inv_n;
    float rstd = rsqrtf(fmaf(-m, m, cs[128 + c] * inv_n) + EPS);
    float a = gamma[c] * rstd;
    float bb = fmaf(-a, m, beta[c]);
    int r0 = blockIdx.x * 16;
    #pragma unroll 4
    for (int r = r0; r < r0 + 16; ++r) {
        float v = fmaf(x[(size_t)r * 128 + c], a, bb);
        v = fmaxf(v, 0.f);
        v += g_vn[batch[r] * 128 + c];
        float vo = __shfl_down_sync(0xffffffffu, v, 1);
        if ((c & 1) == 0) {
            __half2 h = __floats2half2_rn(v, vo);
            out16[r * 64 + (c >> 1)] = *(unsigned*)&h;
        }
    }
}

__global__ void bn_apply_final(const float* __restrict__ x, const float* __restrict__ gamma,
                               const float* __restrict__ beta, const float* __restrict__ cs,
                               unsigned* __restrict__ out16, float* __restrict__ anchor) {
    int c = threadIdx.x;
    const float inv_n = 1.f / N_NODES;
    float m = cs[c] * inv_n;
    float rstd = rsqrtf(fmaf(-m, m, cs[128 + c] * inv_n) + EPS);
    float a = gamma[c] * rstd;
    float bb = fmaf(-a, m, beta[c]);
    int r0 = blockIdx.x * 16;
    #pragma unroll 4
    for (int r = r0; r < r0 + 16; ++r) {
        float v = fmaf(x[(size_t)r * 128 + c], a, bb);
        anchor[(size_t)r * 128 + c] = v;
        float vo = __shfl_down_sync(0xffffffffu, v, 1);
        if ((c & 1) == 0) {
            __half2 h = __floats2half2_rn(v, vo);
            out16[r * 64 + (c >> 1)] = *(unsigned*)&h;
        }
    }
}

// ---------------- fused vn-MLP (layer 0 only; layer-1 MLP is dead code) ----------------
__global__ void k_vtz(const __half* __restrict__ h, const float* __restrict__ W1,
                      const float* __restrict__ b1, float* __restrict__ z,
                      float* __restrict__ csZ) {
    __shared__ float vt_s[128];
    __shared__ float part[256];
    int g = blockIdx.x, tid = threadIdx.x;
    int c = tid & 127, hlf = tid >> 7;
    int s = g_gstart[g], e = g_gstart[g + 1];
    int nh = (e - s) >> 1;
    int rs = hlf ? s + nh : s;
    int re = hlf ? e : s + nh;
    float acc = 0.f;
    for (int r = rs; r < re; ++r) acc += __half2float(h[(size_t)r * 128 + c]);
    part[tid] = acc;
    __syncthreads();
    if (tid < 128) vt_s[tid] = part[tid] + part[tid + 128] + g_vn[g * 128 + tid];
    __syncthreads();
    float zacc = b1[tid];
    #pragma unroll 4
    for (int k = 0; k < 128; ++k) zacc = fmaf(vt_s[k], W1[k * 256 + tid], zacc);
    z[g * 256 + tid] = zacc;
    atomicAdd(&csZ[tid], zacc);
    atomicAdd(&csZ[256 + tid], zacc * zacc);
}

__global__ void k_t(const float* __restrict__ z, const float* __restrict__ g1,
                    const float* __restrict__ bt1, const float* __restrict__ W2,
                    const float* __restrict__ b2, float* __restrict__ t,
                    const float* __restrict__ csZ, float* __restrict__ csT) {
    __shared__ float zb[256];
    int g = blockIdx.x, c = threadIdx.x;
    const float inv = 1.f / NG;
    #pragma unroll
    for (int k = 0; k < 2; ++k) {
        int col = c + k * 128;
        float m = csZ[col] * inv;
        float rs = rsqrtf(fmaf(-m, m, csZ[256 + col] * inv) + EPS);
        float v = z[g * 256 + col];
        zb[col] = fmaxf(fmaf(g1[col] * (v - m), rs, bt1[col]), 0.f);
    }
    __syncthreads();
    float acc = b2[c];
    #pragma unroll 4
    for (int k = 0; k < 256; ++k) acc = fmaf(zb[k], W2[k * 128 + c], acc);
    t[g * 128 + c] = acc;
    atomicAdd(&csT[c], acc);
    atomicAdd(&csT[128 + c], acc * acc);
}

__global__ void k_vnup(const float* __restrict__ t, const float* __restrict__ g2,
                       const float* __restrict__ bt2, const float* __restrict__ csT) {
    int g = blockIdx.x, c = threadIdx.x;
    const float inv = 1.f / NG;
    float m = csT[c] * inv;
    float rs = rsqrtf(fmaf(-m, m, csT[128 + c] * inv) + EPS);
    float v = t[g * 128 + c];
    g_vn[g * 128 + c] += fmaxf(fmaf(g2[c] * (v - m), rs, bt2[c]), 0.f);
}

// ---------------- fused segment mean pool + output head ----------------
__global__ void k_pool_head(const __half* __restrict__ h, const float* __restrict__ Wout,
                            const float* __restrict__ bout, float* __restrict__ out) {
    __shared__ float pool_s[128];
    int g = blockIdx.x, c = threadIdx.x;
    int s = g_gstart[g], e = g_gstart[g + 1];
    float acc = 0.f;
    int r = s;
    for (; r + 4 <= e; r += 4) {
        float a0 = __half2float(h[(size_t)(r + 0) * 128 + c]);
        float a1 = __half2float(h[(size_t)(r + 1) * 128 + c]);
        float a2 = __half2float(h[(size_t)(r + 2) * 128 + c]);
        float a3 = __half2float(h[(size_t)(r + 3) * 128 + c]);
        acc += (a0 + a1) + (a2 + a3);
    }
    for (; r < e; ++r) acc += __half2float(h[(size_t)r * 128 + c]);
    pool_s[c] = acc / fmaxf((float)(e - s), 1.f);
    __syncthreads();
    float o = bout[c];
    #pragma unroll 4
    for (int k = 0; k < 128; ++k) o = fmaf(pool_s[k], Wout[k * 128 + c], o);
    out[g * 128 + c] = o;
}

// ---------------- host orchestration ----------------
extern "C" void kernel_launch(void* const* d_in, const int* in_sizes, int n_in,
                              void* d_out, int out_size) {
    const float* x      = (const float*)d_in[0];
    const int*   ei     = (const int*)d_in[1];
    const int*   src    = ei;
    const int*   dst    = ei + N_EDGES;
    const int*   batch  = (const int*)d_in[2];
    const float* W      = (const float*)d_in[3];
    const float* b      = (const float*)d_in[4];
    const float* gamma  = (const float*)d_in[5];
    const float* beta   = (const float*)d_in[6];
    const float* vn_emb = (const float*)d_in[7];
    const float* W1     = (const float*)d_in[8];
    const float* b1     = (const float*)d_in[9];
    const float* g1     = (const float*)d_in[10];
    const float* bt1    = (const float*)d_in[11];
    const float* W2     = (const float*)d_in[12];
    const float* b2     = (const float*)d_in[13];
    const float* g2     = (const float*)d_in[14];
    const float* bt2    = (const float*)d_in[15];
    const float* Wout   = (const float*)d_in[16];
    const float* bout   = (const float*)d_in[17];
    float* out = (float*)d_out;

    float *anchor, *buf2, *z, *t, *cs;
    __half* wh;
    uint2 *ha, *hb;
    cudaGetSymbolAddress((void**)&anchor, g_anchor);
    cudaGetSymbolAddress((void**)&buf2, g_buf2);
    cudaGetSymbolAddress((void**)&ha,   g_ha);
    cudaGetSymbolAddress((void**)&hb,   g_hb);
    cudaGetSymbolAddress((void**)&wh,   g_wh);
    cudaGetSymbolAddress((void**)&z,    g_z);
    cudaGetSymbolAddress((void**)&t,    g_t);
    cudaGetSymbolAddress((void**)&cs,   g_cs);

    const int MMA_SMEM = 2 * 128 * PITCH * 2 + 256 * 4;  // 70656 bytes
    cudaFuncSetAttribute(gemm_mma, cudaFuncAttributeMaxDynamicSharedMemorySize, MMA_SMEM);

    cudaStream_t s2;
    cudaStreamCreateWithFlags(&s2, cudaStreamNonBlocking);
    cudaEvent_t evStart, evS2, evH0, evVN;
    cudaEventCreateWithFlags(&evStart, cudaEventDisableTiming);
    cudaEventCreateWithFlags(&evS2,    cudaEventDisableTiming);
    cudaEventCreateWithFlags(&evH0,    cudaEventDisableTiming);
    cudaEventCreateWithFlags(&evVN,    cudaEventDisableTiming);

    // ---- setup (fork: pre runs parallel to CSR build) ----
    k_init<<<256, 256>>>(vn_emb, W);
    cudaEventRecord(evStart, 0);
    cudaStreamWaitEvent(s2, evStart, 0);
    k_pre<<<(N_NODES * 32 + 255) / 256, 256, 0, s2>>>(batch, (const float4*)x, ha);
    cudaEventRecord(evS2, s2);

    k_hist<<<(N_EDGES + 255) / 256, 256>>>(dst);
    k_scan1<<<NBLK, 1024>>>();
    k_scan3<<<NBLK, 1024>>>();
    k_fill<<<(N_EDGES + 255) / 256, 256>>>(src, dst);
    cudaStreamWaitEvent(0, evS2, 0);

    const int PROP_BLOCKS = (N_NODES * 32 + 255) / 256;
    const int MMA_BLOCKS = (N_NODES + 127) / 128;
    const int BN_BLOCKS = N_NODES / 16;
    float* csZ = cs + 3 * 512;
    float* csT = cs + 4 * 512;

    // ---- layer 0 ----
    k_prop_h<<<PROP_BLOCKS, 256>>>(ha, hb);
    gemm_mma<<<MMA_BLOCKS, 256, MMA_SMEM>>>((const __half*)hb, wh, b, buf2, cs);
    bn_apply_layer<<<BN_BLOCKS, 128>>>(buf2, gamma, beta, batch, cs, (unsigned*)ha);
    cudaEventRecord(evH0, 0);

    // vn-MLP (j=1 torch wraparound) on side stream, overlapped with layer-1 prop+gemm
    cudaStreamWaitEvent(s2, evH0, 0);
    k_vtz<<<NG, 256, 0, s2>>>((const __half*)ha, W1 + 1 * 128 * 256, b1 + 1 * 256, z, csZ);
    k_t<<<NG, 128, 0, s2>>>(z, g1 + 1 * 256, bt1 + 1 * 256, W2 + 1 * 256 * 128,
                            b2 + 1 * 128, t, csZ, csT);
    k_vnup<<<NG, 128, 0, s2>>>(t, g2 + 1 * 128, bt2 + 1 * 128, csT);
    cudaEventRecord(evVN, s2);

    // ---- layer 1 ----
    k_prop_h<<<PROP_BLOCKS, 256>>>(ha, hb);
    gemm_mma<<<MMA_BLOCKS, 256, MMA_SMEM>>>((const __half*)hb, wh + HID * HID,
                                            b + 128, buf2, cs + 512);
    cudaStreamWaitEvent(0, evVN, 0);
    bn_apply_layer<<<BN_BLOCKS, 128>>>(buf2, gamma + 128, beta + 128, batch,
                                       cs + 512, (unsigned*)ha);
    // layer-1's vn-MLP only updates vn, never read again -> dead code, elided.

    // ---- final conv + BN (no activation); anchor kept fp32 ----
    k_prop_h<<<PROP_BLOCKS, 256>>>(ha, hb);
    gemm_mma<<<MMA_BLOCKS, 256, MMA_SMEM>>>((const __half*)hb, wh + 2 * HID * HID,
                                            b + 2 * 128, buf2, cs + 2 * 512);
    bn_apply_final<<<BN_BLOCKS, 128>>>(buf2, gamma + 2 * 128, beta + 2 * 128,
                                       cs + 2 * 512, (unsigned*)ha, anchor);

    // ---- APPNP: 5 ping-pong props ----
    uint2* s = ha;
    uint2* d = hb;
    for (int k = 0; k < 5; k++) {
        k_prop_ap<<<PROP_BLOCKS, 256>>>(s, (const float4*)anchor, d);
        uint2* tmp = s; s = d; d = tmp;
    }

    // ---- fused segment mean pool + head ----
    k_pool_head<<<NG, 128>>>((const __half*)s, Wout, bout, out);
}

// round 9
// speedup vs baseline: 1.0753x; 1.0753x over previous
#include <cuda_runtime.h>
#include <cuda_fp16.h>

#define N_NODES 50000
#define N_EDGES 600000
#define HID 128
#define NG 512
#define EPS 1e-5f
#define NBLK ((N_NODES + 1023) / 1024)   // 49
#define PITCH 136                         // smem half pitch (272B, ldmatrix conflict-free)

// PDL entry sync: wait for full completion of the upstream grid (no early trigger
// is ever issued, so ordering semantics are identical to a normal launch).
#define GDS() cudaGridDependencySynchronize()

// ---------------- device scratch ----------------
__device__ float  g_anchor[N_NODES * HID]; // fp32 APPNP anchor h0
__device__ float  g_buf2[N_NODES * HID];   // gemm output (pre-BN)
__device__ uint2  g_ha[N_NODES * 32];      // half feature buffer A
__device__ uint2  g_hb[N_NODES * 32];      // half feature buffer B
__device__ __half g_wh[3 * HID * HID];     // half conv weights
__device__ int    g_deg[N_NODES];
__device__ float  g_dinv[N_NODES];
__device__ int    g_rowptr[N_NODES + 1];
__device__ int    g_cursor[N_NODES];
__device__ int    g_bsum[NBLK];
__device__ int2   g_epack[N_EDGES];        // packed {src, weight bits}
__device__ int    g_gstart[NG + 1];        // graph segment starts (batch is sorted)
__device__ float  g_vn[NG * HID];
__device__ float  g_z[NG * 2 * HID];
__device__ float  g_t[NG * HID];
__device__ float  g_cs[8 * 512];           // per-BN-instance column sum/sumsq

// ---------------- half helpers ----------------
__device__ __forceinline__ float4 h2f4(uint2 u) {
    __half2 a = *(__half2*)&u.x, b = *(__half2*)&u.y;
    float2 fa = __half22float2(a), fb = __half22float2(b);
    return make_float4(fa.x, fa.y, fb.x, fb.y);
}
__device__ __forceinline__ uint2 f2h4(float4 v) {
    __half2 a = __floats2half2_rn(v.x, v.y), b = __floats2half2_rn(v.z, v.w);
    uint2 u;
    u.x = *(unsigned*)&a;
    u.y = *(unsigned*)&b;
    return u;
}

// ---------------- setup ----------------
__global__ void k_init(const float* __restrict__ vn_emb, const float* __restrict__ W) {
    int i = blockIdx.x * blockDim.x + threadIdx.x;
    if (i < N_NODES) g_deg[i] = 0;
    if (i < NG * HID) g_vn[i] = vn_emb[i & (HID - 1)];
    if (i < 3 * HID * HID) g_wh[i] = __float2half(W[i]);
    if (i < 8 * 512) g_cs[i] = 0.f;
}

// fused: graph segment starts + x -> half conversion
__global__ void k_pre(const int* __restrict__ batch, const float4* __restrict__ x,
                      uint2* __restrict__ out) {
    int i = blockIdx.x * blockDim.x + threadIdx.x;
    if (i < N_NODES * 32) out[i] = f2h4(x[i]);
    if (i < N_NODES) {
        int b = batch[i];
        int bp = (i == 0) ? -1 : batch[i - 1];
        for (int g = bp + 1; g <= b; ++g) g_gstart[g] = i;
        if (i == N_NODES - 1) {
            for (int g = b + 1; g <= NG; ++g) g_gstart[g] = N_NODES;
        }
    }
}

__global__ void k_hist(const int* __restrict__ dst) {
    GDS();
    int e = blockIdx.x * blockDim.x + threadIdx.x;
    if (e < N_EDGES) atomicAdd(&g_deg[dst[e]], 1);
}

__global__ void k_scan1() {
    GDS();
    __shared__ int ws[32];
    int tid = threadIdx.x;
    int i = blockIdx.x * 1024 + tid;
    int v = (i < N_NODES) ? g_deg[i] : 0;
    if (i < N_NODES) g_dinv[i] = rsqrtf((float)(v + 1));
    int r = v;
    #pragma unroll
    for (int o = 16; o; o >>= 1) r += __shfl_down_sync(0xffffffffu, r, o);
    if ((tid & 31) == 0) ws[tid >> 5] = r;
    __syncthreads();
    if (tid < 32) {
        int t = ws[tid];
        #pragma unroll
        for (int o = 16; o; o >>= 1) t += __shfl_down_sync(0xffffffffu, t, o);
        if (tid == 0) g_bsum[blockIdx.x] = t;
    }
}

// fused scan: each block computes its chunk offset from g_bsum, then intra-chunk scan
__global__ void k_scan3() {
    GDS();
    __shared__ int wsum[32];
    __shared__ int sb[64];
    int tid = threadIdx.x;
    if (tid < 64) {
        int v = (tid < NBLK) ? g_bsum[tid] : 0;
        sb[tid] = v;
    }
    __syncthreads();
    #pragma unroll
    for (int o = 1; o < 64; o <<= 1) {
        int u = 0;
        if (tid < 64 && tid >= o) u = sb[tid - o];
        __syncthreads();
        if (tid < 64) sb[tid] += u;
        __syncthreads();
    }
    if (blockIdx.x == 0 && tid == NBLK - 1) g_rowptr[N_NODES] = sb[tid];
    int boff = (blockIdx.x == 0) ? 0 : sb[blockIdx.x - 1];

    int i = blockIdx.x * 1024 + tid;
    int v = (i < N_NODES) ? g_deg[i] : 0;
    int x = v;
    #pragma unroll
    for (int o = 1; o < 32; o <<= 1) {
        int y = __shfl_up_sync(0xffffffffu, x, o);
        if ((tid & 31) >= o) x += y;
    }
    if ((tid & 31) == 31) wsum[tid >> 5] = x;
    __syncthreads();
    if (tid < 32) {
        int s = wsum[tid];
        int z = s;
        #pragma unroll
        for (int o = 1; o < 32; o <<= 1) {
            int y = __shfl_up_sync(0xffffffffu, z, o);
            if (tid >= o) z += y;
        }
        wsum[tid] = z - s;
    }
    __syncthreads();
    int excl = boff + (x - v) + wsum[tid >> 5];
    if (i < N_NODES) { g_rowptr[i] = excl; g_cursor[i] = excl; }
}

__global__ void k_fill(const int* __restrict__ src, const int* __restrict__ dst) {
    GDS();
    int e = blockIdx.x * blockDim.x + threadIdx.x;
    if (e >= N_EDGES) return;
    int d = dst[e], s = src[e];
    int pos = atomicAdd(&g_cursor[d], 1);
    g_epack[pos] = make_int2(s, __float_as_int(g_dinv[s] * g_dinv[d]));
}

// ---------------- propagation (half gather, packed edges; proven 2-way loop) -------
__device__ __forceinline__ float4 gather(const uint2* __restrict__ in, int node, int lane) {
    float dv = g_dinv[node];
    float w0 = dv * dv;
    float4 p = h2f4(__ldg(&in[node * 32 + lane]));
    float4 acc = make_float4(w0 * p.x, w0 * p.y, w0 * p.z, w0 * p.w);
    int e = __ldg(&g_rowptr[node]), end = __ldg(&g_rowptr[node + 1]);
    for (; e + 1 < end; e += 2) {
        int2 e0 = __ldg(&g_epack[e]);
        int2 e1 = __ldg(&g_epack[e + 1]);
        float w0e = __int_as_float(e0.y);
        float w1e = __int_as_float(e1.y);
        float4 q0 = h2f4(__ldg(&in[e0.x * 32 + lane]));
        float4 q1 = h2f4(__ldg(&in[e1.x * 32 + lane]));
        acc.x = fmaf(w0e, q0.x, acc.x); acc.y = fmaf(w0e, q0.y, acc.y);
        acc.z = fmaf(w0e, q0.z, acc.z); acc.w = fmaf(w0e, q0.w, acc.w);
        acc.x = fmaf(w1e, q1.x, acc.x); acc.y = fmaf(w1e, q1.y, acc.y);
        acc.z = fmaf(w1e, q1.z, acc.z); acc.w = fmaf(w1e, q1.w, acc.w);
    }
    if (e < end) {
        int2 e0 = __ldg(&g_epack[e]);
        float w0e = __int_as_float(e0.y);
        float4 q0 = h2f4(__ldg(&in[e0.x * 32 + lane]));
        acc.x = fmaf(w0e, q0.x, acc.x); acc.y = fmaf(w0e, q0.y, acc.y);
        acc.z = fmaf(w0e, q0.z, acc.z); acc.w = fmaf(w0e, q0.w, acc.w);
    }
    return acc;
}

// layer prop: half output (GEMM A operand)
__global__ void k_prop_h(const uint2* __restrict__ in, uint2* __restrict__ out) {
    GDS();
    int node = (blockIdx.x * blockDim.x + threadIdx.x) >> 5;
    if (node >= N_NODES) return;
    int lane = threadIdx.x & 31;
    out[node * 32 + lane] = f2h4(gather(in, node, lane));
}

__global__ void k_prop_ap(const uint2* __restrict__ in, const float4* __restrict__ h0,
                          uint2* __restrict__ out) {
    GDS();
    int node = (blockIdx.x * blockDim.x + threadIdx.x) >> 5;
    if (node >= N_NODES) return;
    int lane = threadIdx.x & 31;
    float4 acc = gather(in, node, lane);
    float4 a0 = __ldg(&h0[node * 32 + lane]);
    float4 o = make_float4(fmaf(0.2f, acc.x, 0.8f * a0.x), fmaf(0.2f, acc.y, 0.8f * a0.y),
                           fmaf(0.2f, acc.z, 0.8f * a0.z), fmaf(0.2f, acc.w, 0.8f * a0.w));
    out[node * 32 + lane] = f2h4(o);
}

// ---------------- tensor-core GEMM (HMMA m16n8k16, fp32 acc, fused BN stats) ----------
__device__ __forceinline__ void ldsm_x4(unsigned addr, unsigned& r0, unsigned& r1,
                                        unsigned& r2, unsigned& r3) {
    asm volatile("ldmatrix.sync.aligned.m8n8.x4.shared.b16 {%0,%1,%2,%3}, [%4];"
                 : "=r"(r0), "=r"(r1), "=r"(r2), "=r"(r3) : "r"(addr));
}
__device__ __forceinline__ void ldsm_x4t(unsigned addr, unsigned& r0, unsigned& r1,
                                         unsigned& r2, unsigned& r3) {
    asm volatile("ldmatrix.sync.aligned.m8n8.x4.trans.shared.b16 {%0,%1,%2,%3}, [%4];"
                 : "=r"(r0), "=r"(r1), "=r"(r2), "=r"(r3) : "r"(addr));
}
__device__ __forceinline__ void mma16816(float* d, unsigned a0, unsigned a1, unsigned a2,
                                         unsigned a3, unsigned b0, unsigned b1) {
    asm volatile(
        "mma.sync.aligned.m16n8k16.row.col.f32.f16.f16.f32 "
        "{%0,%1,%2,%3},{%4,%5,%6,%7},{%8,%9},{%0,%1,%2,%3};"
        : "+f"(d[0]), "+f"(d[1]), "+f"(d[2]), "+f"(d[3])
        : "r"(a0), "r"(a1), "r"(a2), "r"(a3), "r"(b0), "r"(b1));
}

__global__ void __launch_bounds__(256) gemm_mma(
        const __half* __restrict__ A, const __half* __restrict__ Wh,
        const float* __restrict__ bias, float* __restrict__ C,
        float* __restrict__ cs) {
    GDS();
    extern __shared__ __half sh[];
    __half* As = sh;                       // 128 x PITCH
    __half* Ws = sh + 128 * PITCH;         // 128 x PITCH
    float* scs = (float*)(sh + 2 * 128 * PITCH);  // 256 floats
    int tid = threadIdx.x;
    scs[tid] = 0.f;
    int r0 = blockIdx.x * 128;
    #pragma unroll
    for (int it = 0; it < 8; ++it) {
        int i = tid + it * 256;
        int row = i >> 4, cu = i & 15;
        uint4 v = make_uint4(0u, 0u, 0u, 0u);
        if (r0 + row < N_NODES) v = *(const uint4*)(A + (size_t)(r0 + row) * 128 + cu * 8);
        *(uint4*)(As + row * PITCH + cu * 8) = v;
        *(uint4*)(Ws + row * PITCH + cu * 8) = *(const uint4*)(Wh + row * 128 + cu * 8);
    }
    __syncthreads();

    int wid = tid >> 5, lane = tid & 31;
    int wm = wid >> 1, wn = wid & 1;
    float acc[2][8][4];
    #pragma unroll
    for (int a = 0; a < 2; a++)
        #pragma unroll
        for (int b = 0; b < 8; b++)
            #pragma unroll
            for (int c = 0; c < 4; c++) acc[a][b][c] = 0.f;

    unsigned asBase = (unsigned)__cvta_generic_to_shared(As);
    unsigned wsBase = (unsigned)__cvta_generic_to_shared(Ws);
    unsigned aAddr = asBase + (unsigned)(((wm * 32 + (lane & 15)) * PITCH + (lane >> 4) * 8) * 2);
    unsigned bAddr = wsBase + (unsigned)(((lane & 15) * PITCH + wn * 64 + (lane >> 4) * 8) * 2);

    #pragma unroll
    for (int ks = 0; ks < 8; ++ks) {
        unsigned a0r[4], a1r[4];
        ldsm_x4(aAddr + ks * 32, a0r[0], a0r[1], a0r[2], a0r[3]);
        ldsm_x4(aAddr + ks * 32 + 16 * PITCH * 2, a1r[0], a1r[1], a1r[2], a1r[3]);
        unsigned br[4][4];
        #pragma unroll
        for (int nfp = 0; nfp < 4; nfp++)
            ldsm_x4t(bAddr + ks * 16 * PITCH * 2 + nfp * 32,
                     br[nfp][0], br[nfp][1], br[nfp][2], br[nfp][3]);
        #pragma unroll
        for (int nfp = 0; nfp < 4; nfp++) {
            mma16816(acc[0][2 * nfp],     a0r[0], a0r[1], a0r[2], a0r[3], br[nfp][0], br[nfp][1]);
            mma16816(acc[0][2 * nfp + 1], a0r[0], a0r[1], a0r[2], a0r[3], br[nfp][2], br[nfp][3]);
            mma16816(acc[1][2 * nfp],     a1r[0], a1r[1], a1r[2], a1r[3], br[nfp][0], br[nfp][1]);
            mma16816(acc[1][2 * nfp + 1], a1r[0], a1r[1], a1r[2], a1r[3], br[nfp][2], br[nfp][3]);
        }
    }

    int cb = wn * 64;
    #pragma unroll
    for (int nf = 0; nf < 8; ++nf) {
        int col = cb + nf * 8 + (lane & 3) * 2;
        float b0 = __ldg(&bias[col]), b1 = __ldg(&bias[col + 1]);
        float s0 = 0.f, s1 = 0.f, q0 = 0.f, q1 = 0.f;
        #pragma unroll
        for (int mf = 0; mf < 2; ++mf) {
            int r = r0 + wm * 32 + mf * 16 + (lane >> 2);
            float v0 = acc[mf][nf][0] + b0, v1 = acc[mf][nf][1] + b1;
            if (r < N_NODES) {
                *(float2*)&C[(size_t)r * 128 + col] = make_float2(v0, v1);
                s0 += v0; s1 += v1;
                q0 = fmaf(v0, v0, q0); q1 = fmaf(v1, v1, q1);
            }
            int r2 = r + 8;
            float v2 = acc[mf][nf][2] + b0, v3 = acc[mf][nf][3] + b1;
            if (r2 < N_NODES) {
                *(float2*)&C[(size_t)r2 * 128 + col] = make_float2(v2, v3);
                s0 += v2; s1 += v3;
                q0 = fmaf(v2, v2, q0); q1 = fmaf(v3, v3, q1);
            }
        }
        #pragma unroll
        for (int off = 16; off >= 4; off >>= 1) {
            s0 += __shfl_xor_sync(0xffffffffu, s0, off);
            s1 += __shfl_xor_sync(0xffffffffu, s1, off);
            q0 += __shfl_xor_sync(0xffffffffu, q0, off);
            q1 += __shfl_xor_sync(0xffffffffu, q1, off);
        }
        if (lane < 4) {
            atomicAdd(&scs[col], s0);
            atomicAdd(&scs[col + 1], s1);
            atomicAdd(&scs[128 + col], q0);
            atomicAdd(&scs[128 + col + 1], q1);
        }
    }
    __syncthreads();
    atomicAdd(&cs[tid], scs[tid]);
}

// ---------------- BN apply (16 rows/block, no atomics) ----------------
__global__ void bn_apply_layer(const float* __restrict__ x, const float* __restrict__ gamma,
                               const float* __restrict__ beta, const int* __restrict__ batch,
                               const float* __restrict__ cs, unsigned* __restrict__ out16) {
    GDS();
    int c = threadIdx.x;
    const float inv_n = 1.f / N_NODES;
    float m = cs[c] * inv_n;
    float rstd = rsqrtf(fmaf(-m, m, cs[128 + c] * inv_n) + EPS);
    float a = gamma[c] * rstd;
    float bb = fmaf(-a, m, beta[c]);
    int r0 = blockIdx.x * 16;
    #pragma unroll 4
    for (int r = r0; r < r0 + 16; ++r) {
        float v = fmaf(x[(size_t)r * 128 + c], a, bb);
        v = fmaxf(v, 0.f);
        v += g_vn[batch[r] * 128 + c];
        float vo = __shfl_down_sync(0xffffffffu, v, 1);
        if ((c & 1) == 0) {
            __half2 h = __floats2half2_rn(v, vo);
            out16[r * 64 + (c >> 1)] = *(unsigned*)&h;
        }
    }
}

__global__ void bn_apply_final(const float* __restrict__ x, const float* __restrict__ gamma,
                               const float* __restrict__ beta, const float* __restrict__ cs,
                               unsigned* __restrict__ out16, float* __restrict__ anchor) {
    GDS();
    int c = threadIdx.x;
    const float inv_n = 1.f / N_NODES;
    float m = cs[c] * inv_n;
    float rstd = rsqrtf(fmaf(-m, m, cs[128 + c] * inv_n) + EPS);
    float a = gamma[c] * rstd;
    float bb = fmaf(-a, m, beta[c]);
    int r0 = blockIdx.x * 16;
    #pragma unroll 4
    for (int r = r0; r < r0 + 16; ++r) {
        float v = fmaf(x[(size_t)r * 128 + c], a, bb);
        anchor[(size_t)r * 128 + c] = v;
        float vo = __shfl_down_sync(0xffffffffu, v, 1);
        if ((c & 1) == 0) {
            __half2 h = __floats2half2_rn(v, vo);
            out16[r * 64 + (c >> 1)] = *(unsigned*)&h;
        }
    }
}

// ---------------- fused vn-MLP (layer 0 only; layer-1 MLP is dead code) ----------------
__global__ void k_vtz(const __half* __restrict__ h, const float* __restrict__ W1,
                      const float* __restrict__ b1, float* __restrict__ z,
                      float* __restrict__ csZ) {
    __shared__ float vt_s[128];
    __shared__ float part[256];
    int g = blockIdx.x, tid = threadIdx.x;
    int c = tid & 127, hlf = tid >> 7;
    int s = g_gstart[g], e = g_gstart[g + 1];
    int nh = (e - s) >> 1;
    int rs = hlf ? s + nh : s;
    int re = hlf ? e : s + nh;
    float acc = 0.f;
    for (int r = rs; r < re; ++r) acc += __half2float(h[(size_t)r * 128 + c]);
    part[tid] = acc;
    __syncthreads();
    if (tid < 128) vt_s[tid] = part[tid] + part[tid + 128] + g_vn[g * 128 + tid];
    __syncthreads();
    float zacc = b1[tid];
    #pragma unroll 4
    for (int k = 0; k < 128; ++k) zacc = fmaf(vt_s[k], W1[k * 256 + tid], zacc);
    z[g * 256 + tid] = zacc;
    atomicAdd(&csZ[tid], zacc);
    atomicAdd(&csZ[256 + tid], zacc * zacc);
}

__global__ void k_t(const float* __restrict__ z, const float* __restrict__ g1,
                    const float* __restrict__ bt1, const float* __restrict__ W2,
                    const float* __restrict__ b2, float* __restrict__ t,
                    const float* __restrict__ csZ, float* __restrict__ csT) {
    __shared__ float zb[256];
    int g = blockIdx.x, c = threadIdx.x;
    const float inv = 1.f / NG;
    #pragma unroll
    for (int k = 0; k < 2; ++k) {
        int col = c + k * 128;
        float m = csZ[col] * inv;
        float rs = rsqrtf(fmaf(-m, m, csZ[256 + col] * inv) + EPS);
        float v = z[g * 256 + col];
        zb[col] = fmaxf(fmaf(g1[col] * (v - m), rs, bt1[col]), 0.f);
    }
    __syncthreads();
    float acc = b2[c];
    #pragma unroll 4
    for (int k = 0; k < 256; ++k) acc = fmaf(zb[k], W2[k * 128 + c], acc);
    t[g * 128 + c] = acc;
    atomicAdd(&csT[c], acc);
    atomicAdd(&csT[128 + c], acc * acc);
}

__global__ void k_vnup(const float* __restrict__ t, const float* __restrict__ g2,
                       const float* __restrict__ bt2, const float* __restrict__ csT) {
    int g = blockIdx.x, c = threadIdx.x;
    const float inv = 1.f / NG;
    float m = csT[c] * inv;
    float rs = rsqrtf(fmaf(-m, m, csT[128 + c] * inv) + EPS);
    float v = t[g * 128 + c];
    g_vn[g * 128 + c] += fmaxf(fmaf(g2[c] * (v - m), rs, bt2[c]), 0.f);
}

// ---------------- fused segment mean pool + output head ----------------
__global__ void k_pool_head(const __half* __restrict__ h, const float* __restrict__ Wout,
                            const float* __restrict__ bout, float* __restrict__ out) {
    GDS();
    __shared__ float pool_s[128];
    int g = blockIdx.x, c = threadIdx.x;
    int s = g_gstart[g], e = g_gstart[g + 1];
    float acc = 0.f;
    int r = s;
    for (; r + 4 <= e; r += 4) {
        float a0 = __half2float(h[(size_t)(r + 0) * 128 + c]);
        float a1 = __half2float(h[(size_t)(r + 1) * 128 + c]);
        float a2 = __half2float(h[(size_t)(r + 2) * 128 + c]);
        float a3 = __half2float(h[(size_t)(r + 3) * 128 + c]);
        acc += (a0 + a1) + (a2 + a3);
    }
    for (; r < e; ++r) acc += __half2float(h[(size_t)r * 128 + c]);
    pool_s[c] = acc / fmaxf((float)(e - s), 1.f);
    __syncthreads();
    float o = bout[c];
    #pragma unroll 4
    for (int k = 0; k < 128; ++k) o = fmaf(pool_s[k], Wout[k * 128 + c], o);
    out[g * 128 + c] = o;
}

// ---------------- PDL launch helper ----------------
#define PDL_LAUNCH(grid_, block_, smem_, kern_, ...) do {                        \
    cudaLaunchConfig_t _cfg = {};                                                \
    _cfg.gridDim = dim3(grid_); _cfg.blockDim = dim3(block_);                    \
    _cfg.dynamicSmemBytes = (smem_); _cfg.stream = 0;                            \
    cudaLaunchAttribute _attr[1];                                                \
    _attr[0].id = cudaLaunchAttributeProgrammaticStreamSerialization;            \
    _attr[0].val.programmaticStreamSerializationAllowed = 1;                     \
    _cfg.attrs = _attr; _cfg.numAttrs = 1;                                       \
    cudaLaunchKernelEx(&_cfg, kern_, ##__VA_ARGS__);                             \
} while (0)

// ---------------- host orchestration ----------------
extern "C" void kernel_launch(void* const* d_in, const int* in_sizes, int n_in,
                              void* d_out, int out_size) {
    const float* x      = (const float*)d_in[0];
    const int*   ei     = (const int*)d_in[1];
    const int*   src    = ei;
    const int*   dst    = ei + N_EDGES;
    const int*   batch  = (const int*)d_in[2];
    const float* W      = (const float*)d_in[3];
    const float* b      = (const float*)d_in[4];
    const float* gamma  = (const float*)d_in[5];
    const float* beta   = (const float*)d_in[6];
    const float* vn_emb = (const float*)d_in[7];
    const float* W1     = (const float*)d_in[8];
    const float* b1     = (const float*)d_in[9];
    const float* g1     = (const float*)d_in[10];
    const float* bt1    = (const float*)d_in[11];
    const float* W2     = (const float*)d_in[12];
    const float* b2     = (const float*)d_in[13];
    const float* g2     = (const float*)d_in[14];
    const float* bt2    = (const float*)d_in[15];
    const float* Wout   = (const float*)d_in[16];
    const float* bout   = (const float*)d_in[17];
    float* out = (float*)d_out;

    float *anchor, *buf2, *z, *t, *cs;
    __half* wh;
    uint2 *ha, *hb;
    cudaGetSymbolAddress((void**)&anchor, g_anchor);
    cudaGetSymbolAddress((void**)&buf2, g_buf2);
    cudaGetSymbolAddress((void**)&ha,   g_ha);
    cudaGetSymbolAddress((void**)&hb,   g_hb);
    cudaGetSymbolAddress((void**)&wh,   g_wh);
    cudaGetSymbolAddress((void**)&z,    g_z);
    cudaGetSymbolAddress((void**)&t,    g_t);
    cudaGetSymbolAddress((void**)&cs,   g_cs);

    const int MMA_SMEM = 2 * 128 * PITCH * 2 + 256 * 4;  // 70656 bytes
    cudaFuncSetAttribute(gemm_mma, cudaFuncAttributeMaxDynamicSharedMemorySize, MMA_SMEM);

    cudaStream_t s2;
    cudaStreamCreateWithFlags(&s2, cudaStreamNonBlocking);
    cudaEvent_t evStart, evS2, evH0, evVN;
    cudaEventCreateWithFlags(&evStart, cudaEventDisableTiming);
    cudaEventCreateWithFlags(&evS2,    cudaEventDisableTiming);
    cudaEventCreateWithFlags(&evH0,    cudaEventDisableTiming);
    cudaEventCreateWithFlags(&evVN,    cudaEventDisableTiming);

    // ---- setup (fork: pre runs parallel to CSR build) ----
    k_init<<<256, 256>>>(vn_emb, W);
    cudaEventRecord(evStart, 0);
    cudaStreamWaitEvent(s2, evStart, 0);
    k_pre<<<(N_NODES * 32 + 255) / 256, 256, 0, s2>>>(batch, (const float4*)x, ha);
    cudaEventRecord(evS2, s2);

    PDL_LAUNCH((N_EDGES + 255) / 256, 256, 0, k_hist, dst);
    PDL_LAUNCH(NBLK, 1024, 0, k_scan1);
    PDL_LAUNCH(NBLK, 1024, 0, k_scan3);
    PDL_LAUNCH((N_EDGES + 255) / 256, 256, 0, k_fill, src, dst);
    cudaStreamWaitEvent(0, evS2, 0);

    const int PROP_BLOCKS = (N_NODES * 32 + 255) / 256;
    const int MMA_BLOCKS = (N_NODES + 127) / 128;
    const int BN_BLOCKS = N_NODES / 16;
    float* csZ = cs + 3 * 512;
    float* csT = cs + 4 * 512;

    // ---- layer 0 ----
    k_prop_h<<<PROP_BLOCKS, 256>>>(ha, hb);  // after event wait: plain launch
    PDL_LAUNCH(MMA_BLOCKS, 256, MMA_SMEM, gemm_mma,
               (const __half*)hb, (const __half*)wh, b, buf2, (float*)cs);
    PDL_LAUNCH(BN_BLOCKS, 128, 0, bn_apply_layer,
               (const float*)buf2, gamma, beta, batch, (const float*)cs, (unsigned*)ha);
    cudaEventRecord(evH0, 0);

    // vn-MLP (j=1 torch wraparound) on side stream, overlapped with layer-1 prop+gemm
    cudaStreamWaitEvent(s2, evH0, 0);
    k_vtz<<<NG, 256, 0, s2>>>((const __half*)ha, W1 + 1 * 128 * 256, b1 + 1 * 256, z, csZ);
    k_t<<<NG, 128, 0, s2>>>(z, g1 + 1 * 256, bt1 + 1 * 256, W2 + 1 * 256 * 128,
                            b2 + 1 * 128, t, csZ, csT);
    k_vnup<<<NG, 128, 0, s2>>>(t, g2 + 1 * 128, bt2 + 1 * 128, csT);
    cudaEventRecord(evVN, s2);

    // ---- layer 1 ----
    PDL_LAUNCH(PROP_BLOCKS, 256, 0, k_prop_h, (const uint2*)ha, hb);
    PDL_LAUNCH(MMA_BLOCKS, 256, MMA_SMEM, gemm_mma,
               (const __half*)hb, (const __half*)(wh + HID * HID), (const float*)(b + 128),
               buf2, (float*)(cs + 512));
    cudaStreamWaitEvent(0, evVN, 0);
    bn_apply_layer<<<BN_BLOCKS, 128>>>(buf2, gamma + 128, beta + 128, batch,
                                       cs + 512, (unsigned*)ha);  // after event wait: plain
    // layer-1's vn-MLP only updates vn, never read again -> dead code, elided.

    // ---- final conv + BN (no activation); anchor kept fp32 ----
    PDL_LAUNCH(PROP_BLOCKS, 256, 0, k_prop_h, (const uint2*)ha, hb);
    PDL_LAUNCH(MMA_BLOCKS, 256, MMA_SMEM, gemm_mma,
               (const __half*)hb, (const __half*)(wh + 2 * HID * HID),
               (const float*)(b + 2 * 128), buf2, (float*)(cs + 2 * 512));
    PDL_LAUNCH(BN_BLOCKS, 128, 0, bn_apply_final,
               (const float*)buf2, (const float*)(gamma + 2 * 128),
               (const float*)(beta + 2 * 128), (const float*)(cs + 2 * 512),
               (unsigned*)ha, anchor);

    // ---- APPNP: 5 ping-pong props ----
    uint2* s = ha;
    uint2* d = hb;
    for (int k = 0; k < 5; k++) {
        PDL_LAUNCH(PROP_BLOCKS, 256, 0, k_prop_ap,
                   (const uint2*)s, (const float4*)anchor, d);
        uint2* tmp = s; s = d; d = tmp;
    }

    // ---- fused segment mean pool + head ----
    PDL_LAUNCH(NG, 128, 0, k_pool_head, (const __half*)s, Wout, bout, out);
}